// round 12
// baseline (speedup 1.0000x reference)
#include <cuda_runtime.h>

#define W 512
#define H 512
#define B 16
#define HW (H*W)

#define TX 64
#define TY 32

// Scratch: grayscale image (device global, no allocation)
__device__ float g_gray[B * HW];

// ---------------------------------------------------------------------------
// Kernel 1: gray + channel shuffle. Each thread: 2 float4 chunks (MLP=6).
// ---------------------------------------------------------------------------
__global__ __launch_bounds__(256) void k1_gray_shuffle(
    const float* __restrict__ x, const int* __restrict__ perm,
    float* __restrict__ x5)
{
    const int nv = HW / 4;          // float4 per channel-plane
    const int half = nv / 2;
    int t = blockIdx.x * 256 + threadIdx.x;
    if (t >= B * half) return;
    int b = t / half;
    int p = t - b * half;

    const float4* xb = (const float4*)(x + (size_t)b * 3 * HW);
    float4 c0a = xb[p],          c0b = xb[p + half];
    float4 c1a = xb[nv + p],     c1b = xb[nv + p + half];
    float4 c2a = xb[2*nv + p],   c2b = xb[2*nv + p + half];

    float4 ga, gb;
    ga.x = 0.114f*c0a.x + 0.587f*c1a.x + 0.299f*c2a.x;
    ga.y = 0.114f*c0a.y + 0.587f*c1a.y + 0.299f*c2a.y;
    ga.z = 0.114f*c0a.z + 0.587f*c1a.z + 0.299f*c2a.z;
    ga.w = 0.114f*c0a.w + 0.587f*c1a.w + 0.299f*c2a.w;
    gb.x = 0.114f*c0b.x + 0.587f*c1b.x + 0.299f*c2b.x;
    gb.y = 0.114f*c0b.y + 0.587f*c1b.y + 0.299f*c2b.y;
    gb.z = 0.114f*c0b.z + 0.587f*c1b.z + 0.299f*c2b.z;
    gb.w = 0.114f*c0b.w + 0.587f*c1b.w + 0.299f*c2b.w;
    ((float4*)g_gray)[b * nv + p]        = ga;
    ((float4*)g_gray)[b * nv + p + half] = gb;

    int p0 = perm[b * 3 + 0];
    int p1 = perm[b * 3 + 1];
    int p2 = perm[b * 3 + 2];
    float4* o = (float4*)(x5 + (size_t)b * 3 * HW);
    o[p]               = (p0 == 0) ? c0a : ((p0 == 1) ? c1a : c2a);
    o[p + half]        = (p0 == 0) ? c0b : ((p0 == 1) ? c1b : c2b);
    o[nv + p]          = (p1 == 0) ? c0a : ((p1 == 1) ? c1a : c2a);
    o[nv + p + half]   = (p1 == 0) ? c0b : ((p1 == 1) ? c1b : c2b);
    o[2*nv + p]        = (p2 == 0) ? c0a : ((p2 == 1) ? c1a : c2a);
    o[2*nv + p + half] = (p2 == 0) ? c0b : ((p2 == 1) ? c1b : c2b);
}

// ---------------------------------------------------------------------------
// Fused kernel: gaussian(reflect) -> sobel(replicate) -> magnitude ->
// NMS(zero pad) -> 4 dilations (SAME max-pool k=3,5,7,9), all in smem.
// 64x32 output tile per block, 512 threads.
//
// smem pool (48384 B) with overlapping live ranges:
//   ss   @     0 (40x72 f)  stage E..G      st @ 0 (48x76 f) stages B..C
//   smag @ 11520 (42x74 f)  stages D..E     v* @ 11520 (4x 32x72 f) stages F..G
//   sax  @ 23952 (40x72 u8) stages D..E
//   sb   @ 26832 (44x76 f)  stages C..D
//   sg   @ 14592 (48x80 f)  stages A..B
// ---------------------------------------------------------------------------
__device__ __forceinline__ int refl(int i, int n) {
    if (i < 0) i = -i;
    if (i >= n) i = 2 * n - 2 - i;
    return i;
}

__global__ __launch_bounds__(512) void kF_canny_dilate(
    float* __restrict__ outmag,
    float* __restrict__ o3, float* __restrict__ o5,
    float* __restrict__ o7, float* __restrict__ o9)
{
    __shared__ __align__(16) char pool[48384];
    float* ss            = (float*)(pool + 0);        // 40x72
    float* st            = (float*)(pool + 0);        // 48x76 (dead before ss written)
    float* smag          = (float*)(pool + 11520);    // 42x74
    unsigned char* sax   = (unsigned char*)(pool + 23952); // 40x72
    float* sb            = (float*)(pool + 26832);    // 44x76
    float* sg            = (float*)(pool + 14592);    // 48x80
    float* v3            = (float*)(pool + 11520);              // 32x72
    float* v5            = (float*)(pool + 11520 +  9216);
    float* v7            = (float*)(pool + 11520 + 18432);
    float* v9            = (float*)(pool + 11520 + 27648);

    const int tid = threadIdx.x;
    const int b = blockIdx.z;
    const int ty0 = blockIdx.y * TY;
    const int tx0 = blockIdx.x * TX;
    const float* g = g_gray + (size_t)b * HW;
    const bool xborder = (blockIdx.x == 0) | (blockIdx.x == (W/TX - 1));

    // ---- Stage A: gray load, rows ty0-8..ty0+39 (refl), cols tx0-8..tx0+71
    if (!xborder) {
        for (int i = tid; i < 48 * 20; i += 512) {
            int r = i / 20, c4 = i - 20 * r;
            int gyr = refl(ty0 + r - 8, H);
            const float4* row = (const float4*)(g + gyr * W + tx0 - 8);
            *(float4*)&sg[r * 80 + c4 * 4] = row[c4];
        }
    } else {
        for (int i = tid; i < 48 * 80; i += 512) {
            int r = i / 80, c = i - 80 * r;
            sg[r * 80 + c] = g[refl(ty0 + r - 8, H) * W + refl(tx0 + c - 8, W)];
        }
    }
    __syncthreads();

    const float w0 = 0.05448868f, w1 = 0.24420136f, w2 = 0.40261996f;

    // ---- Stage B: horizontal blur. st (48x76): cols tx0-6..tx0+69
    for (int i = tid; i < 48 * 76; i += 512) {
        int r = i / 76, c = i - 76 * r;
        const float* p = &sg[r * 80 + c];
        st[i] = w0 * (p[0] + p[4]) + w1 * (p[1] + p[3]) + w2 * p[2];
    }
    __syncthreads();

    // ---- Stage C: vertical blur. sb (44x76): rows ty0-6..ty0+37
    for (int i = tid; i < 44 * 76; i += 512) {
        int r = i / 76, c = i - 76 * r;
        const float* p = &st[r * 76 + c];
        sb[i] = w0 * (p[0] + p[4 * 76]) + w1 * (p[76] + p[3 * 76]) + w2 * p[2 * 76];
    }
    __syncthreads();

    // ---- Stage D: magnitude smag (42x74): rows ty0-5..ty0+36, cols tx0-5..tx0+68
    // sobel neighbors replicate-clamp to image; 0 outside image.
    // Also compute NMS axis for the 40x72 ss region (smag r 1..40, c 1..72).
    for (int i = tid; i < 42 * 74; i += 512) {
        int r = i / 74, c = i - 74 * r;
        int gy = ty0 + r - 5, gx = tx0 + c - 5;
        float v = 0.f;
        if (gy >= 0 && gy < H && gx >= 0 && gx < W) {
            int ym = max(gy - 1, 0) - ty0 + 6;
            int yc = gy - ty0 + 6;
            int yp = min(gy + 1, H - 1) - ty0 + 6;
            int xm = max(gx - 1, 0) - tx0 + 6;
            int xc = gx - tx0 + 6;
            int xp = min(gx + 1, W - 1) - tx0 + 6;
            float b00 = sb[ym * 76 + xm], b01 = sb[ym * 76 + xc], b02 = sb[ym * 76 + xp];
            float b10 = sb[yc * 76 + xm],                          b12 = sb[yc * 76 + xp];
            float b20 = sb[yp * 76 + xm], b21 = sb[yp * 76 + xc], b22 = sb[yp * 76 + xp];
            float gxv = (b02 - b00) + 2.f * (b12 - b10) + (b22 - b20);
            float gyv = (b20 - b00) + 2.f * (b21 - b01) + (b22 - b02);
            v = sqrtf(gxv * gxv + gyv * gyv + 1e-6f);

            if ((unsigned)(r - 1) < 40u && (unsigned)(c - 1) < 72u) {
                float ax = fabsf(gxv), ay = fabsf(gyv);
                int axis;
                if (ay < 0.41421356f * ax)      axis = 0;   // tan(22.5)
                else if (ay > 2.41421356f * ax) axis = 2;   // tan(67.5)
                else axis = (gxv * gyv >= 0.f) ? 1 : 3;
                sax[(r - 1) * 72 + (c - 1)] = (unsigned char)axis;
            }
        }
        smag[i] = v;
    }
    __syncthreads();

    // ---- Stage E: NMS. ss (40x72): rows ty0-4..ty0+35, cols tx0-4..tx0+67
    for (int i = tid; i < 40 * 72; i += 512) {
        int rs = i / 72, cs = i - 72 * rs;
        int gy = ty0 + rs - 4, gx = tx0 + cs - 4;
        float r = 0.f;
        if (gy >= 0 && gy < H && gx >= 0 && gx < W) {
            int axis = sax[i];
            int dy = (axis == 0) ? 0 : 1;
            int dx = (axis == 2) ? 0 : ((axis == 3) ? -1 : 1);
            float m   = smag[(rs + 1) * 74 + (cs + 1)];
            float pos = m - smag[(rs + 1 + dy) * 74 + (cs + 1 + dx)];
            float neg = m - smag[(rs + 1 - dy) * 74 + (cs + 1 - dx)];
            r = (fminf(pos, neg) > 0.f) ? m : 0.f;
        }
        ss[i] = r;
    }
    __syncthreads();

    // ---- Stage F: vertical incremental maxes for output rows 0..31, all 72 cols
    for (int i = tid; i < 32 * 72; i += 512) {
        int r = i / 72, c = i - 72 * r;
        const float* p = &ss[r * 72 + c];
        float t3 = fmaxf(fmaxf(p[3 * 72], p[4 * 72]), p[5 * 72]);
        float t5 = fmaxf(t3, fmaxf(p[2 * 72], p[6 * 72]));
        float t7 = fmaxf(t5, fmaxf(p[1 * 72], p[7 * 72]));
        float t9 = fmaxf(t7, fmaxf(p[0],      p[8 * 72]));
        v3[i] = t3; v5[i] = t5; v7[i] = t7; v9[i] = t9;
    }
    __syncthreads();

    // ---- Stage G: horizontal maxes + all stores (mag + 4 dilations), float4
    {
        int i = tid;                       // exactly 512 work items
        int y = i / 16, x4 = (i - 16 * y) * 4;

        // suppressed magnitude output (central part of ss)
        float4 mg = *(const float4*)&ss[(y + 4) * 72 + (x4 + 4)];

        float4 r3, r5, r7, r9;
        float *p3 = (float*)&r3, *p5 = (float*)&r5, *p7 = (float*)&r7, *p9 = (float*)&r9;
        #pragma unroll
        for (int j = 0; j < 4; j++) {
            int base = y * 72 + x4 + j;    // center col is x+4
            float a3 = fmaxf(fmaxf(v3[base + 3], v3[base + 4]), v3[base + 5]);
            float a5 = fmaxf(fmaxf(v5[base + 2], v5[base + 3]),
                       fmaxf(v5[base + 4], fmaxf(v5[base + 5], v5[base + 6])));
            float a7 = fmaxf(fmaxf(fmaxf(v7[base + 1], v7[base + 2]),
                                   fmaxf(v7[base + 3], v7[base + 4])),
                             fmaxf(fmaxf(v7[base + 5], v7[base + 6]), v7[base + 7]));
            float a9 = fmaxf(fmaxf(fmaxf(fmaxf(v9[base + 0], v9[base + 1]),
                                         fmaxf(v9[base + 2], v9[base + 3])),
                                   fmaxf(fmaxf(v9[base + 4], v9[base + 5]),
                                         fmaxf(v9[base + 6], v9[base + 7]))),
                             v9[base + 8]);
            p3[j] = a3; p5[j] = a5; p7[j] = a7; p9[j] = a9;
        }
        size_t o = (size_t)b * HW + (size_t)(ty0 + y) * W + tx0 + x4;
        *(float4*)&outmag[o] = mg;
        *(float4*)&o3[o] = r3;
        *(float4*)&o5[o] = r5;
        *(float4*)&o7[o] = r7;
        *(float4*)&o9[o] = r9;
    }
}

// ---------------------------------------------------------------------------
extern "C" void kernel_launch(void* const* d_in, const int* in_sizes, int n_in,
                              void* d_out, int out_size)
{
    const float* x    = (const float*)d_in[0];
    const int*   perm = (const int*)d_in[1];
    float* out = (float*)d_out;

    float* o_mag = out;
    float* o_d3  = out + 1 * (size_t)B * HW;
    float* o_d5  = out + 2 * (size_t)B * HW;
    float* o_d7  = out + 3 * (size_t)B * HW;
    float* o_d9  = out + 4 * (size_t)B * HW;
    float* o_x5  = out + 5 * (size_t)B * HW;

    int nthreads1 = B * (HW / 8);   // 2 float4 chunks per thread
    k1_gray_shuffle<<<(nthreads1 + 255) / 256, 256>>>(x, perm, o_x5);

    dim3 g2(W / TX, H / TY, B);
    kF_canny_dilate<<<g2, 512>>>(o_mag, o_d3, o_d5, o_d7, o_d9);
}